// round 15
// baseline (speedup 1.0000x reference)
#include <cuda_runtime.h>
#include <cuda_bf16.h>

#define PP 4096   // patches (64x64)
#define SS 64
#define HH 32
#define EE 34
#define NN 8192   // B(=2) * P

// ---------------- device scratch (no allocations allowed) ----------------
__device__ float g_h[NN * HH];
__device__ float g_Q[NN * EE];
__device__ float g_K[NN * EE];
__device__ float g_V[NN * EE];

__device__ __forceinline__ float warp_sum(float v) {
#pragma unroll
    for (int o = 16; o > 0; o >>= 1) v += __shfl_xor_sync(0xffffffffu, v, o);
    return v;
}

// ===========================================================================
// Kernel A: hnew = tanh(inp@Wx^T + h@Wh^T + bx + bh); qin=[hnew, r/64, c/64];
//           Q/K/V = qin @ Win^T + bin   (Win rows 0..33 / 34..67 / 68..101)
// Warp-per-row. Lane j owns output column j; weights in registers; inputs
// staged in shared, read via broadcast float4.
// ===========================================================================
__global__ void __launch_bounds__(256, 1) stepA(
    const float* __restrict__ inp,
    const float* __restrict__ Wx, const float* __restrict__ bx,
    const float* __restrict__ Wh, const float* __restrict__ bh,
    const float* __restrict__ Win, const float* __restrict__ bin,
    int first, int N)
{
    const int lane = threadIdx.x & 31;
    const int wid  = threadIdx.x >> 5;

    __shared__ __align__(16) float s_in[8][32];
    __shared__ __align__(16) float s_h [8][32];
    __shared__ __align__(16) float s_hn[8][32];

    // per-lane weight columns (lane = output index)
    float w1[32], w2[32], wq[32], wk[32], wv[32];
#pragma unroll
    for (int k = 0; k < 32; k++) {
        w1[k] = Wx[lane * 32 + k];
        w2[k] = Wh[lane * 32 + k];
        wq[k] = Win[ lane        * 34 + k];
        wk[k] = Win[(34  + lane) * 34 + k];
        wv[k] = Win[(68  + lane) * 34 + k];
    }
    const float cq0 = Win[ lane       * 34 + 32], cq1 = Win[ lane       * 34 + 33];
    const float ck0 = Win[(34 + lane) * 34 + 32], ck1 = Win[(34 + lane) * 34 + 33];
    const float cv0 = Win[(68 + lane) * 34 + 32], cv1 = Win[(68 + lane) * 34 + 33];
    // weights for the 6 overflow output rows (Q:32,33  K:66,67  V:100,101)
    const float xq0 = Win[ 32 * 34 + lane], xq1 = Win[ 33 * 34 + lane];
    const float xk0 = Win[ 66 * 34 + lane], xk1 = Win[ 67 * 34 + lane];
    const float xv0 = Win[100 * 34 + lane], xv1 = Win[101 * 34 + lane];
    // coord weights + bias for the overflow rows, held by lanes 0..5
    int xrow = (lane < 2) ? (32 + lane) : (lane < 4) ? (64 + lane) : (96 + lane);
    float xcr = 0.f, xcc = 0.f, xb = 0.f;
    if (lane < 6) {
        xcr = Win[xrow * 34 + 32];
        xcc = Win[xrow * 34 + 33];
        xb  = bin[xrow];
    }
    const float b12 = bx[lane] + bh[lane];
    const float bq = bin[lane], bk_ = bin[34 + lane], bv = bin[68 + lane];

    const int warp_g = (blockIdx.x << 3) + wid;
    const int nwarps = gridDim.x << 3;

    for (int n = warp_g; n < N; n += nwarps) {
        const float in_val = inp[n * 32 + lane];
        const float h_val  = first ? 0.f : g_h[n * 32 + lane];
        __syncwarp();
        s_in[wid][lane] = in_val;
        s_h [wid][lane] = h_val;
        __syncwarp();

        // ---- tanh RNN ----
        float a0 = b12, a1 = 0.f, a2 = 0.f, a3 = 0.f;
        const float4* pi = (const float4*)s_in[wid];
        const float4* ph = (const float4*)s_h [wid];
#pragma unroll
        for (int j = 0; j < 8; j++) {
            float4 xi = pi[j], xh = ph[j];
            a0 += xi.x * w1[4*j+0]; a1 += xi.y * w1[4*j+1];
            a2 += xi.z * w1[4*j+2]; a3 += xi.w * w1[4*j+3];
            a0 += xh.x * w2[4*j+0]; a1 += xh.y * w2[4*j+1];
            a2 += xh.z * w2[4*j+2]; a3 += xh.w * w2[4*j+3];
        }
        const float hn = tanhf((a0 + a1) + (a2 + a3));

        __syncwarp();
        s_hn[wid][lane] = hn;
        __syncwarp();

        const int p = n & (PP - 1);
        const float r64 = (float)(p >> 6) * 0.015625f;
        const float c64 = (float)(p & 63) * 0.015625f;

        // ---- Q/K/V (main 32 output dims) ----
        float q0 = bq,  q1 = 0.f;
        float k0 = bk_, k1 = 0.f;
        float v0 = bv,  v1 = 0.f;
        const float4* pn = (const float4*)s_hn[wid];
#pragma unroll
        for (int j = 0; j < 8; j++) {
            float4 xh = pn[j];
            q0 += xh.x * wq[4*j+0]; q1 += xh.y * wq[4*j+1];
            q0 += xh.z * wq[4*j+2]; q1 += xh.w * wq[4*j+3];
            k0 += xh.x * wk[4*j+0]; k1 += xh.y * wk[4*j+1];
            k0 += xh.z * wk[4*j+2]; k1 += xh.w * wk[4*j+3];
            v0 += xh.x * wv[4*j+0]; v1 += xh.y * wv[4*j+1];
            v0 += xh.z * wv[4*j+2]; v1 += xh.w * wv[4*j+3];
        }
        const float qv = q0 + q1 + r64 * cq0 + c64 * cq1;
        const float kv = k0 + k1 + r64 * ck0 + c64 * ck1;
        const float vv = v0 + v1 + r64 * cv0 + c64 * cv1;

        g_h[n * 32 + lane] = hn;
        g_Q[n * 34 + lane] = qv;
        g_K[n * 34 + lane] = kv;
        g_V[n * 34 + lane] = vv;

        // ---- overflow output dims (6 warp reductions) ----
        const float e0 = warp_sum(hn * xq0);
        const float e1 = warp_sum(hn * xq1);
        const float e2 = warp_sum(hn * xk0);
        const float e3 = warp_sum(hn * xk1);
        const float e4 = warp_sum(hn * xv0);
        const float e5 = warp_sum(hn * xv1);
        if (lane < 6) {
            float ev = (lane == 0) ? e0 : (lane == 1) ? e1 : (lane == 2) ? e2
                     : (lane == 3) ? e3 : (lane == 4) ? e4 : e5;
            ev += r64 * xcr + c64 * xcc + xb;
            if      (lane < 2) g_Q[n * 34 + 32 + lane]       = ev;
            else if (lane < 4) g_K[n * 34 + 32 + (lane - 2)] = ev;
            else               g_V[n * 34 + 32 + (lane - 4)] = ev;
        }
    }
}

// ===========================================================================
// Kernel B: 9-neighbor center attention + Wout + fcsa residual + fc2 + LN
// ===========================================================================
__global__ void __launch_bounds__(256, 1) stepB(
    const float* __restrict__ Wout, const float* __restrict__ bout,
    const float* __restrict__ Wfcsa, const float* __restrict__ bfcsa,
    const float* __restrict__ Wfc2, const float* __restrict__ bfc2,
    const float* __restrict__ ln_g, const float* __restrict__ ln_b,
    float* __restrict__ pred, int N)
{
    const int lane = threadIdx.x & 31;
    const int wid  = threadIdx.x >> 5;

    __shared__ __align__(16) float s_o [8][36];
    __shared__ __align__(16) float s_ao[8][36];
    __shared__ __align__(16) float s_hn[8][32];

    // weights (lane = output index)
    float wo[34], wf[34], wc2[32];
#pragma unroll
    for (int e = 0; e < 34; e++) {
        wo[e] = Wout [lane * 34 + e];
        wf[e] = Wfcsa[lane * 34 + e];
    }
#pragma unroll
    for (int k = 0; k < 32; k++) wc2[k] = Wfc2[lane * 32 + k];
    // Wout overflow rows 32,33: per-lane column weights + tail scalars on lanes 0/1
    const float xwo0 = Wout[32 * 34 + lane];
    const float xwo1 = Wout[33 * 34 + lane];
    float t0 = 0.f, t1 = 0.f, tb = 0.f;
    if (lane < 2) {
        t0 = Wout[(32 + lane) * 34 + 32];
        t1 = Wout[(32 + lane) * 34 + 33];
        tb = bout[32 + lane];
    }
    const float bo = bout[lane], bf = bfcsa[lane], b2 = bfc2[lane];
    const float lg = ln_g[lane], lb = ln_b[lane];
    const float scale = 0.17149858514250882f; // 1/sqrt(34)

    const int warp_g = (blockIdx.x << 3) + wid;
    const int nwarps = gridDim.x << 3;

    for (int n = warp_g; n < N; n += nwarps) {
        const int p = n & (PP - 1);
        const int bbase = n - p;               // b * P
        const int r = p >> 6, c = p & 63;
        const int rr = r + (r == 0) - (r == 63);
        const int cc = c + (c == 0) - (c == 63);
        int nb[9];
#pragma unroll
        for (int m = 0; m < 9; m++)
            nb[m] = bbase + ((rr + m / 3 - 1) << 6) + (cc + m % 3 - 1);

        // ---- scores: q(center) . k(neighbor m) ----
        const float* qp = g_Q + (size_t)nb[4] * 34;
        const float qv = qp[lane];
        const float qt = (lane < 2) ? qp[32 + lane] : 0.f;
        float sc[9];
#pragma unroll
        for (int m = 0; m < 9; m++) {
            const float* kp = g_K + (size_t)nb[m] * 34;
            float part = qv * kp[lane];
            if (lane < 2) part += qt * kp[32 + lane];
            sc[m] = warp_sum(part) * scale;
        }
        // ---- softmax over 9 (redundant in all lanes) ----
        float mx = sc[0];
#pragma unroll
        for (int m = 1; m < 9; m++) mx = fmaxf(mx, sc[m]);
        float den = 0.f;
#pragma unroll
        for (int m = 0; m < 9; m++) { sc[m] = expf(sc[m] - mx); den += sc[m]; }
        const float rden = 1.0f / den;

        // ---- o = sum_m w_m * V[nb[m]] ----
        float o = 0.f, ot = 0.f;
#pragma unroll
        for (int m = 0; m < 9; m++) {
            const float w = sc[m] * rden;
            const float* vp = g_V + (size_t)nb[m] * 34;
            o += w * vp[lane];
            if (lane < 2) ot += w * vp[32 + lane];
        }
        __syncwarp();
        s_o[wid][lane] = o;
        if (lane < 2) s_o[wid][32 + lane] = ot;
        __syncwarp();

        // ---- ao = o @ Wout^T + bout ----
        float a0 = bo, a1 = 0.f, a2 = 0.f, a3 = 0.f;
        const float4* po = (const float4*)s_o[wid];
#pragma unroll
        for (int j = 0; j < 8; j++) {
            float4 x = po[j];
            a0 += x.x * wo[4*j+0]; a1 += x.y * wo[4*j+1];
            a2 += x.z * wo[4*j+2]; a3 += x.w * wo[4*j+3];
        }
        const float o32 = s_o[wid][32], o33 = s_o[wid][33];
        float ao = (a0 + a1) + (a2 + a3) + o32 * wo[32] + o33 * wo[33];
        // overflow outputs 32, 33
        const float ex0 = warp_sum(o * xwo0);
        const float ex1 = warp_sum(o * xwo1);
        s_ao[wid][lane] = ao;
        if (lane < 2) {
            float ev = ((lane == 0) ? ex0 : ex1) + o32 * t0 + o33 * t1 + tb;
            s_ao[wid][32 + lane] = ev;
        }
        __syncwarp();

        // ---- h += ao @ Wfcsa^T + bfcsa ----
        float f0 = bf, f1 = 0.f, f2 = 0.f, f3 = 0.f;
        const float4* pa = (const float4*)s_ao[wid];
#pragma unroll
        for (int j = 0; j < 8; j++) {
            float4 x = pa[j];
            f0 += x.x * wf[4*j+0]; f1 += x.y * wf[4*j+1];
            f2 += x.z * wf[4*j+2]; f3 += x.w * wf[4*j+3];
        }
        float hn = g_h[n * 32 + lane] + (f0 + f1) + (f2 + f3)
                 + s_ao[wid][32] * wf[32] + s_ao[wid][33] * wf[33];
        g_h[n * 32 + lane] = hn;
        s_hn[wid][lane] = hn;
        __syncwarp();

        // ---- y = h @ Wfc2^T + bfc2; LayerNorm ----
        float y0 = b2, y1 = 0.f, y2 = 0.f, y3 = 0.f;
        const float4* pnh = (const float4*)s_hn[wid];
#pragma unroll
        for (int j = 0; j < 8; j++) {
            float4 x = pnh[j];
            y0 += x.x * wc2[4*j+0]; y1 += x.y * wc2[4*j+1];
            y2 += x.z * wc2[4*j+2]; y3 += x.w * wc2[4*j+3];
        }
        const float y = (y0 + y1) + (y2 + y3);
        const float mean = warp_sum(y) * 0.03125f;
        const float d = y - mean;
        const float var = warp_sum(d * d) * 0.03125f;
        pred[(size_t)n * 32 + lane] = d * rsqrtf(var + 1e-5f) * lg + lb;
    }
}

// ===========================================================================
extern "C" void kernel_launch(void* const* d_in, const int* in_sizes, int n_in,
                              void* d_out, int out_size) {
    const float* x     = (const float*)d_in[0];
    const float* Wx    = (const float*)d_in[1];
    const float* bx    = (const float*)d_in[2];
    const float* Wh    = (const float*)d_in[3];
    const float* bh    = (const float*)d_in[4];
    const float* Wfc2  = (const float*)d_in[5];
    const float* bfc2  = (const float*)d_in[6];
    const float* lng   = (const float*)d_in[7];
    const float* lnb   = (const float*)d_in[8];
    const float* Wfcsa = (const float*)d_in[9];
    const float* bfcsa = (const float*)d_in[10];
    const float* Win   = (const float*)d_in[11];
    const float* bin   = (const float*)d_in[12];
    const float* Wout  = (const float*)d_in[13];
    const float* bout  = (const float*)d_in[14];
    float* out = (float*)d_out;

    const int N = in_sizes[0] / (10 * 32);   // 8192 (B=2)
    const dim3 grid(148), block(256);

    for (int t = 0; t < 59; t++) {
        const float* inp = (t < 10) ? x + (size_t)t * N * 32
                                    : out + (size_t)(t - 1) * N * 32;
        stepA<<<grid, block>>>(inp, Wx, bx, Wh, bh, Win, bin, (t == 0) ? 1 : 0, N);
        stepB<<<grid, block>>>(Wout, bout, Wfcsa, bfcsa, Wfc2, bfc2, lng, lnb,
                               out + (size_t)t * N * 32, N);
    }
}